// round 11
// baseline (speedup 1.0000x reference)
#include <cuda_runtime.h>
#include <cstdint>

// ---------------------------------------------------------------------------
// sincKAN as 3 GEMMs in PURE FP32 (FFMA) — precision discriminator round.
//   A^T[klin][b] layout, klin = j*I+i: j=0 -> x (skip), j=1+kh*65+d -> sinc
//   W[klin][o]:            j=0 -> alpha[i,o], else coeffs[i,o,kh,d]
//   Y = A@W + beta.
// Exact fp32 products; two-level accumulation (per-BK-tile accumulator folded
// into main acc) keeps summation noise ~1e-7 * |y|.
// sinc(t+k) = (-1)^k * sinpi(t)/(pi*(t+k)) via correctly-rounded __frcp_rn.
// Split-K=8 with deterministic fp32 reduction (+beta).
// ---------------------------------------------------------------------------

#define BATCH   1024
#define SPLITS  8
#define BM      128
#define BN      128
#define BK      16

// Static device scratch (allocation APIs banned; __device__ globals OK)
__device__ float g_x0[BATCH * 256];
__device__ float g_x1[BATCH * 512];
__device__ float g_x2[BATCH * 512];
__device__ float g_A[(size_t)131 * 512 * BATCH];      // A^T: [K][1024], max K=67072
__device__ float g_W[(size_t)131 * 512 * 512];        // [K][O]
__device__ float g_P[(size_t)SPLITS * BATCH * 512];   // split-K partials

// ---------------------------------------------------------------------------
__device__ __forceinline__ void cp16(void* smem_dst, const void* gmem_src) {
    uint32_t s = (uint32_t)__cvta_generic_to_shared(smem_dst);
    asm volatile("cp.async.cg.shared.global [%0], [%1], 16;\n" :: "r"(s), "l"(gmem_src));
}

// ---------------------------------------------------------------------------
__global__ void tanh_kernel(const float* __restrict__ in, float* __restrict__ out, int n) {
    int t = blockIdx.x * blockDim.x + threadIdx.x;
    if (t < n) out[t] = tanhf(in[t]);
}

// ---------------------------------------------------------------------------
// A generation into A^T[klin][b]. Thread t: b = t & 1023, i = t >> 10.
// Stores coalesced across b. sinc = (-1)^d * (sinpi(t)/pi) * rcp_rn(t + d - 32).
// ---------------------------------------------------------------------------
__global__ void agen_kernel(const float* __restrict__ X, int I) {
    const int t = blockIdx.x * blockDim.x + threadIdx.x;
    const int b = t & (BATCH - 1);
    const int i = t >> 10;

    const float x = X[(size_t)b * I + i];
    g_A[(size_t)i * BATCH + b] = x;                    // skip row j=0

    const float xa = tanhf(x);
    const float INV_PI = 0.31830988618379067f;

    #pragma unroll
    for (int kh = 0; kh < 2; kh++) {
        const float tt = xa * (kh ? 8.0f : 4.0f);
        const float sp = sinpif(tt) * INV_PI;          // sin(pi t)/pi
        float* dst = g_A + ((size_t)(1 + kh * 65) * I + i) * BATCH + b;
        const size_t stride = (size_t)I * BATCH;

        #pragma unroll 8
        for (int d = 0; d < 65; d++) {
            float e = tt + (float)(d - 32);
            float sgn = (d & 1) ? -sp : sp;            // (-1)^(d-32) = (-1)^d
            float v = (e == 0.0f) ? 1.0f : sgn * __frcp_rn(e);
            dst[(size_t)d * stride] = v;
        }
    }
}

// ---------------------------------------------------------------------------
// W generation: coeffs (i,o,kh,d) -> rows (1+kh*65+d)*I + i; alpha -> row j=0.
// ---------------------------------------------------------------------------
__global__ void wgen_kernel(const float* __restrict__ C, const float* __restrict__ alpha,
                            int I, int O) {
    const int i  = blockIdx.x;
    const int o0 = blockIdx.y * 64;
    __shared__ float sm[130][65];

    const float* Ci = C + ((size_t)i * O + o0) * 130;
    for (int idx = threadIdx.x; idx < 64 * 130; idx += blockDim.x) {
        int ol = idx / 130, m = idx - ol * 130;
        sm[m][ol] = Ci[(size_t)ol * 130 + m];
    }
    __syncthreads();

    for (int ol = threadIdx.x; ol < 64; ol += blockDim.x)
        g_W[(size_t)i * O + o0 + ol] = alpha[(size_t)i * O + o0 + ol];

    for (int idx = threadIdx.x; idx < 64 * 130; idx += blockDim.x) {
        int m = idx >> 6, ol = idx & 63;
        g_W[((size_t)(1 + m) * I + i) * O + o0 + ol] = sm[m][ol];
    }
}

// ---------------------------------------------------------------------------
// Pure-FP32 SGEMM, split-K: grid (N/BN, M/BM, SPLITS), 256 threads,
// 8x8 micro-tile per thread, double-buffered cp.async,
// per-BK-tile accumulator folded into main acc (two-level summation).
// ---------------------------------------------------------------------------
__global__ void __launch_bounds__(256, 1)
gemm_kernel(int K, int N) {
    __shared__ float As[2][BK][BM + 4];
    __shared__ float Ws[2][BK][BN + 4];

    const int tid = threadIdx.x;
    const int tx  = tid & 15;          // 0..15 -> N
    const int ty  = tid >> 4;          // 0..15 -> M

    const int nBase  = blockIdx.x * BN;
    const int mBase  = blockIdx.y * BM;
    const int Kper   = K / SPLITS;
    const int kSplit = blockIdx.z * Kper;
    const int ntiles = Kper / BK;

    auto loadTiles = [&](int s, int kt) {
        int kg = kSplit + kt * BK;
        #pragma unroll
        for (int r = 0; r < 2; r++) {
            int idx  = tid + r * 256;
            int krow = idx >> 5, c4 = idx & 31;
            cp16(&As[s][krow][c4 * 4], g_A + (size_t)(kg + krow) * BATCH + mBase + c4 * 4);
            cp16(&Ws[s][krow][c4 * 4], g_W + (size_t)(kg + krow) * N     + nBase + c4 * 4);
        }
    };

    float acc[8][8];
    #pragma unroll
    for (int i = 0; i < 8; i++)
        #pragma unroll
        for (int j = 0; j < 8; j++) acc[i][j] = 0.0f;

    loadTiles(0, 0);
    asm volatile("cp.async.commit_group;\n");
    asm volatile("cp.async.wait_group 0;\n");
    __syncthreads();

    for (int kt = 0; kt < ntiles; kt++) {
        const int cur = kt & 1;
        if (kt + 1 < ntiles) loadTiles(cur ^ 1, kt + 1);
        asm volatile("cp.async.commit_group;\n");

        float tAcc[8][8];
        #pragma unroll
        for (int k = 0; k < BK; k++) {
            float a[8], b[8];
            *(float4*)&a[0] = *(const float4*)&As[cur][k][ty * 8];
            *(float4*)&a[4] = *(const float4*)&As[cur][k][ty * 8 + 4];
            *(float4*)&b[0] = *(const float4*)&Ws[cur][k][tx * 8];
            *(float4*)&b[4] = *(const float4*)&Ws[cur][k][tx * 8 + 4];
            if (k == 0) {
                #pragma unroll
                for (int i = 0; i < 8; i++)
                    #pragma unroll
                    for (int j = 0; j < 8; j++) tAcc[i][j] = a[i] * b[j];
            } else {
                #pragma unroll
                for (int i = 0; i < 8; i++)
                    #pragma unroll
                    for (int j = 0; j < 8; j++) tAcc[i][j] += a[i] * b[j];
            }
        }
        #pragma unroll
        for (int i = 0; i < 8; i++)
            #pragma unroll
            for (int j = 0; j < 8; j++) acc[i][j] += tAcc[i][j];

        asm volatile("cp.async.wait_group 0;\n");
        __syncthreads();
    }

    float* P = g_P + (size_t)blockIdx.z * BATCH * N;
    #pragma unroll
    for (int i = 0; i < 8; i++) {
        int row = mBase + ty * 8 + i;
        int col = nBase + tx * 8;
        *(float4*)&P[(size_t)row * N + col]     = *(float4*)&acc[i][0];
        *(float4*)&P[(size_t)row * N + col + 4] = *(float4*)&acc[i][4];
    }
}

// ---------------------------------------------------------------------------
__global__ void reduce_kernel(const float* __restrict__ beta, float* __restrict__ out, int N) {
    const int t = blockIdx.x * blockDim.x + threadIdx.x;
    const int MN = BATCH * N;
    if (t >= MN) return;
    const int o = t % N;
    float acc = beta[o];
    #pragma unroll
    for (int s = 0; s < SPLITS; s++) acc += g_P[(size_t)s * MN + t];
    out[t] = acc;
}

// ---------------------------------------------------------------------------
static void run_layer(const float* xin, const float* C, const float* alpha,
                      const float* beta, float* xout, int I, int O) {
    const int K = 131 * I;
    wgen_kernel<<<dim3(I, O / 64), 256>>>(C, alpha, I, O);
    agen_kernel<<<(BATCH * I) / 256, 256>>>(xin, I);
    gemm_kernel<<<dim3(O / BN, BATCH / BM, SPLITS), 256>>>(K, O);
    reduce_kernel<<<(BATCH * O + 255) / 256, 256>>>(beta, xout, O);
}

extern "C" void kernel_launch(void* const* d_in, const int* in_sizes, int n_in,
                              void* d_out, int out_size) {
    const float* x  = (const float*)d_in[0];
    const float* c0 = (const float*)d_in[1];
    const float* a0 = (const float*)d_in[2];
    const float* b0 = (const float*)d_in[3];
    const float* c1 = (const float*)d_in[4];
    const float* a1 = (const float*)d_in[5];
    const float* b1 = (const float*)d_in[6];
    const float* c2 = (const float*)d_in[7];
    const float* a2 = (const float*)d_in[8];
    const float* b2 = (const float*)d_in[9];
    float* out = (float*)d_out;

    float *px0, *px1, *px2;
    cudaGetSymbolAddress((void**)&px0, g_x0);
    cudaGetSymbolAddress((void**)&px1, g_x1);
    cudaGetSymbolAddress((void**)&px2, g_x2);

    tanh_kernel<<<(BATCH * 256) / 256, 256>>>(x, px0, BATCH * 256);

    run_layer(px0, c0, a0, b0, px1, 256, 512);
    run_layer(px1, c1, a1, b1, px2, 512, 512);
    run_layer(px2, c2, a2, b2, out, 512, 256);
}

// round 12
// speedup vs baseline: 1.0064x; 1.0064x over previous
#include <cuda_runtime.h>
#include <cstdint>

// ---------------------------------------------------------------------------
// sincKAN as 3 GEMMs in PURE FP32 (FFMA).
//   A^T[klin][b] layout, klin = j*I+i: j=0 -> x (skip), j=1+kh*65+d -> sinc
//   W[klin][o]:            j=0 -> alpha[i,o], else coeffs[i,o,kh,d]
//   Y = A@W + beta.
// GEMM is numerically FROZEN (identical to the passing R11 run: exact fp32
// products, two-level accumulation, split-K=8 deterministic reduce).
// This round: agen uses grouped reciprocals (1 MUFU.RCP per 8 sinc terms)
// instead of per-element __frcp_rn  -> 8x less MUFU work, same values +-2ulp.
// ---------------------------------------------------------------------------

#define BATCH   1024
#define SPLITS  8
#define BM      128
#define BN      128
#define BK      16

// Static device scratch (allocation APIs banned; __device__ globals OK)
__device__ float g_x0[BATCH * 256];
__device__ float g_x1[BATCH * 512];
__device__ float g_x2[BATCH * 512];
__device__ float g_A[(size_t)131 * 512 * BATCH];      // A^T: [K][1024], max K=67072
__device__ float g_W[(size_t)131 * 512 * 512];        // [K][O]
__device__ float g_P[(size_t)SPLITS * BATCH * 512];   // split-K partials

// ---------------------------------------------------------------------------
__device__ __forceinline__ void cp16(void* smem_dst, const void* gmem_src) {
    uint32_t s = (uint32_t)__cvta_generic_to_shared(smem_dst);
    asm volatile("cp.async.cg.shared.global [%0], [%1], 16;\n" :: "r"(s), "l"(gmem_src));
}

// ---------------------------------------------------------------------------
__global__ void tanh_kernel(const float* __restrict__ in, float* __restrict__ out, int n) {
    int t = blockIdx.x * blockDim.x + threadIdx.x;
    if (t < n) out[t] = tanhf(in[t]);
}

// ---------------------------------------------------------------------------
// A generation into A^T[klin][b]. Thread t: b = t & 1023, i = t >> 10.
// Stores coalesced across b (warp-contiguous in b).
// sinc(t+k) = (-1)^k * (sinpi(t)/pi) / (t+k); reciprocals grouped by 8:
// one __frcp_rn of the group product, then prefix/suffix reconstruction.
// ---------------------------------------------------------------------------
__global__ void agen_kernel(const float* __restrict__ X, int I) {
    const int t = blockIdx.x * blockDim.x + threadIdx.x;
    const int b = t & (BATCH - 1);
    const int i = t >> 10;

    const float x = X[(size_t)b * I + i];
    g_A[(size_t)i * BATCH + b] = x;                    // skip row j=0

    const float xa = tanhf(x);
    const float INV_PI = 0.31830988618379067f;
    const size_t stride = (size_t)I * BATCH;

    #pragma unroll
    for (int kh = 0; kh < 2; kh++) {
        const float tt = xa * (kh ? 8.0f : 4.0f);
        const float sp = sinpif(tt) * INV_PI;          // sin(pi t)/pi
        float* dst = g_A + ((size_t)(1 + kh * 65) * I + i) * BATCH + b;

        int d = 0;
        #pragma unroll
        for (int g = 0; g < 8; g++) {                  // d = 0..63 in groups of 8
            float e[8], p[8], inv[8];
            bool  z[8];
            #pragma unroll
            for (int j = 0; j < 8; j++) {
                float ee = tt + (float)(d + j - 32);
                z[j] = (ee == 0.0f);
                e[j] = z[j] ? 1.0f : ee;
            }
            p[0] = e[0];
            #pragma unroll
            for (int j = 1; j < 8; j++) p[j] = p[j - 1] * e[j];
            float r = __frcp_rn(p[7]);
            #pragma unroll
            for (int j = 7; j >= 1; j--) { inv[j] = r * p[j - 1]; r *= e[j]; }
            inv[0] = r;
            #pragma unroll
            for (int j = 0; j < 8; j++) {
                int dd = d + j;
                float sgn = (dd & 1) ? -sp : sp;       // (-1)^(dd-32) = (-1)^dd
                dst[(size_t)dd * stride] = z[j] ? 1.0f : sgn * inv[j];
            }
            d += 8;
        }
        {   // d = 64, k = +32 (even)
            float ee = tt + 32.0f;
            dst[(size_t)64 * stride] = (ee == 0.0f) ? 1.0f : sp * __frcp_rn(ee);
        }
    }
}

// ---------------------------------------------------------------------------
// W generation: coeffs (i,o,kh,d) -> rows (1+kh*65+d)*I + i; alpha -> row j=0.
// ---------------------------------------------------------------------------
__global__ void wgen_kernel(const float* __restrict__ C, const float* __restrict__ alpha,
                            int I, int O) {
    const int i  = blockIdx.x;
    const int o0 = blockIdx.y * 64;
    __shared__ float sm[130][65];

    const float* Ci = C + ((size_t)i * O + o0) * 130;
    for (int idx = threadIdx.x; idx < 64 * 130; idx += blockDim.x) {
        int ol = idx / 130, m = idx - ol * 130;
        sm[m][ol] = Ci[(size_t)ol * 130 + m];
    }
    __syncthreads();

    for (int ol = threadIdx.x; ol < 64; ol += blockDim.x)
        g_W[(size_t)i * O + o0 + ol] = alpha[(size_t)i * O + o0 + ol];

    for (int idx = threadIdx.x; idx < 64 * 130; idx += blockDim.x) {
        int m = idx >> 6, ol = idx & 63;
        g_W[((size_t)(1 + m) * I + i) * O + o0 + ol] = sm[m][ol];
    }
}

// ---------------------------------------------------------------------------
// Pure-FP32 SGEMM, split-K: grid (N/BN, M/BM, SPLITS), 256 threads,
// 8x8 micro-tile per thread, double-buffered cp.async,
// per-BK-tile accumulator folded into main acc (two-level summation).
// FROZEN: identical to the R11 passing run.
// ---------------------------------------------------------------------------
__global__ void __launch_bounds__(256, 1)
gemm_kernel(int K, int N) {
    __shared__ float As[2][BK][BM + 4];
    __shared__ float Ws[2][BK][BN + 4];

    const int tid = threadIdx.x;
    const int tx  = tid & 15;          // 0..15 -> N
    const int ty  = tid >> 4;          // 0..15 -> M

    const int nBase  = blockIdx.x * BN;
    const int mBase  = blockIdx.y * BM;
    const int Kper   = K / SPLITS;
    const int kSplit = blockIdx.z * Kper;
    const int ntiles = Kper / BK;

    auto loadTiles = [&](int s, int kt) {
        int kg = kSplit + kt * BK;
        #pragma unroll
        for (int r = 0; r < 2; r++) {
            int idx  = tid + r * 256;
            int krow = idx >> 5, c4 = idx & 31;
            cp16(&As[s][krow][c4 * 4], g_A + (size_t)(kg + krow) * BATCH + mBase + c4 * 4);
            cp16(&Ws[s][krow][c4 * 4], g_W + (size_t)(kg + krow) * N     + nBase + c4 * 4);
        }
    };

    float acc[8][8];
    #pragma unroll
    for (int i = 0; i < 8; i++)
        #pragma unroll
        for (int j = 0; j < 8; j++) acc[i][j] = 0.0f;

    loadTiles(0, 0);
    asm volatile("cp.async.commit_group;\n");
    asm volatile("cp.async.wait_group 0;\n");
    __syncthreads();

    for (int kt = 0; kt < ntiles; kt++) {
        const int cur = kt & 1;
        if (kt + 1 < ntiles) loadTiles(cur ^ 1, kt + 1);
        asm volatile("cp.async.commit_group;\n");

        float tAcc[8][8];
        #pragma unroll
        for (int k = 0; k < BK; k++) {
            float a[8], b[8];
            *(float4*)&a[0] = *(const float4*)&As[cur][k][ty * 8];
            *(float4*)&a[4] = *(const float4*)&As[cur][k][ty * 8 + 4];
            *(float4*)&b[0] = *(const float4*)&Ws[cur][k][tx * 8];
            *(float4*)&b[4] = *(const float4*)&Ws[cur][k][tx * 8 + 4];
            if (k == 0) {
                #pragma unroll
                for (int i = 0; i < 8; i++)
                    #pragma unroll
                    for (int j = 0; j < 8; j++) tAcc[i][j] = a[i] * b[j];
            } else {
                #pragma unroll
                for (int i = 0; i < 8; i++)
                    #pragma unroll
                    for (int j = 0; j < 8; j++) tAcc[i][j] += a[i] * b[j];
            }
        }
        #pragma unroll
        for (int i = 0; i < 8; i++)
            #pragma unroll
            for (int j = 0; j < 8; j++) acc[i][j] += tAcc[i][j];

        asm volatile("cp.async.wait_group 0;\n");
        __syncthreads();
    }

    float* P = g_P + (size_t)blockIdx.z * BATCH * N;
    #pragma unroll
    for (int i = 0; i < 8; i++) {
        int row = mBase + ty * 8 + i;
        int col = nBase + tx * 8;
        *(float4*)&P[(size_t)row * N + col]     = *(float4*)&acc[i][0];
        *(float4*)&P[(size_t)row * N + col + 4] = *(float4*)&acc[i][4];
    }
}

// ---------------------------------------------------------------------------
__global__ void reduce_kernel(const float* __restrict__ beta, float* __restrict__ out, int N) {
    const int t = blockIdx.x * blockDim.x + threadIdx.x;
    const int MN = BATCH * N;
    if (t >= MN) return;
    const int o = t % N;
    float acc = beta[o];
    #pragma unroll
    for (int s = 0; s < SPLITS; s++) acc += g_P[(size_t)s * MN + t];
    out[t] = acc;
}

// ---------------------------------------------------------------------------
static void run_layer(const float* xin, const float* C, const float* alpha,
                      const float* beta, float* xout, int I, int O) {
    const int K = 131 * I;
    wgen_kernel<<<dim3(I, O / 64), 256>>>(C, alpha, I, O);
    agen_kernel<<<(BATCH * I) / 256, 256>>>(xin, I);
    gemm_kernel<<<dim3(O / BN, BATCH / BM, SPLITS), 256>>>(K, O);
    reduce_kernel<<<(BATCH * O + 255) / 256, 256>>>(beta, xout, O);
}

extern "C" void kernel_launch(void* const* d_in, const int* in_sizes, int n_in,
                              void* d_out, int out_size) {
    const float* x  = (const float*)d_in[0];
    const float* c0 = (const float*)d_in[1];
    const float* a0 = (const float*)d_in[2];
    const float* b0 = (const float*)d_in[3];
    const float* c1 = (const float*)d_in[4];
    const float* a1 = (const float*)d_in[5];
    const float* b1 = (const float*)d_in[6];
    const float* c2 = (const float*)d_in[7];
    const float* a2 = (const float*)d_in[8];
    const float* b2 = (const float*)d_in[9];
    float* out = (float*)d_out;

    float *px0, *px1, *px2;
    cudaGetSymbolAddress((void**)&px0, g_x0);
    cudaGetSymbolAddress((void**)&px1, g_x1);
    cudaGetSymbolAddress((void**)&px2, g_x2);

    tanh_kernel<<<(BATCH * 256) / 256, 256>>>(x, px0, BATCH * 256);

    run_layer(px0, c0, a0, b0, px1, 256, 512);
    run_layer(px1, c1, a1, b1, px2, 512, 512);
    run_layer(px2, c2, a2, b2, out, 512, 256);
}